// round 15
// baseline (speedup 1.0000x reference)
#include <cuda_runtime.h>
#include <cuda_fp16.h>
#include <math.h>
#include <stdint.h>
#include <mma.h>

using namespace nvcuda;

// Problem constants
#define B    64
#define T    2048
#define ENC  512
#define DEC  512
#define ATTN 256

// Energy GEMM tiling: 128x256 CTA tile, 8 warps, warp tile 64x64, persistent
#define TILE_M  128
#define KC      64
#define CPT     8
#define NTILES  1024
#define TPB     16
#define EGRID   148

#define A_LD_H  72
#define B_LD_H  264
#define C_LD2   136

#define A_SLOT_B (TILE_M * A_LD_H * 2)
#define B_SLOT_B (KC * B_LD_H * 2)
#define META_B   2048
#define A0_OFF   META_B
#define B0_OFF   (META_B + 2 * A_SLOT_B)
#define C_OFF    (B0_OFF + 2 * B_SLOT_B)
#define C_BYTES  (TILE_M * C_LD2 * 4)
#define DYN_SMEM (C_OFF + C_BYTES)          // 176128

// Context split-T (fused softmax)
#define CSEG     32
#define CT       (T / CSEG)        // 64

// ---- scratch (no allocations allowed) ----
__device__ __half g_enc_h[(size_t)B * T * ENC];
__device__ __half g_We_h[ENC * ATTN];
__device__ float  g_proj_dec[B * ATTN];
__device__ float  g_energy[B * T];
__device__ int    g_mask_is_byte;

// ---------------------------------------------------------------------------
__device__ __forceinline__ uint32_t smem_u32(const void* p) {
    uint32_t a;
    asm("{ .reg .u64 t; cvta.to.shared.u64 t, %1; cvt.u32.u64 %0, t; }" : "=r"(a) : "l"(p));
    return a;
}
__device__ __forceinline__ float fast_tanh(float x) {
    float y; asm("tanh.approx.f32 %0, %1;" : "=f"(y) : "f"(x)); return y;
}
__device__ __forceinline__ void cp_async16(uint32_t s, const void* g) {
    asm volatile("cp.async.cg.shared.global [%0], [%1], 16;" :: "r"(s), "l"(g));
}
#define CP_COMMIT() asm volatile("cp.async.commit_group;" ::: "memory")
#define CP_WAIT(n)  asm volatile("cp.async.wait_group %0;" :: "n"(n) : "memory")

// ---------------------------------------------------------------------------
// Fused prologue: projdec (0-255, 8 accums), convert_we (256-287),
// mask detect (288), zero out_ctx (289).
// ---------------------------------------------------------------------------
__global__ void __launch_bounds__(256)
prep_kernel(const float* __restrict__ dec, const float* __restrict__ Wd,
            const float* __restrict__ We, const unsigned char* __restrict__ mask,
            float* __restrict__ out_ctx) {
    const int blk = blockIdx.x, tid = threadIdx.x;

    if (blk < 256) {
        __shared__ float sd[DEC];
        __shared__ float sp[256];
        const int b = blk >> 2, q = blk & 3;
        const int a = q * 64 + (tid & 63);
        const int kseg = tid >> 6;
        sd[tid]       = dec[b * DEC + tid];
        sd[tid + 256] = dec[b * DEC + tid + 256];
        __syncthreads();
        const float* wp = Wd + (size_t)(kseg * 128) * ATTN + a;
        const float* dp = sd + kseg * 128;
        float ac[8];
        #pragma unroll
        for (int i = 0; i < 8; i++) ac[i] = 0.f;
        #pragma unroll 2
        for (int i = 0; i < 128; i += 8) {
            #pragma unroll
            for (int u = 0; u < 8; u++)
                ac[u] = fmaf(dp[i + u], wp[(size_t)(i + u) * ATTN], ac[u]);
        }
        sp[tid] = ((ac[0] + ac[1]) + (ac[2] + ac[3]))
                + ((ac[4] + ac[5]) + (ac[6] + ac[7]));
        __syncthreads();
        if (tid < 64)
            g_proj_dec[b * ATTN + q * 64 + tid] =
                sp[tid] + sp[tid + 64] + sp[tid + 128] + sp[tid + 192];
    } else if (blk < 288) {
        const int blk2 = blk - 256;
        const float4* in = (const float4*)We;
        uint2* out = (uint2*)g_We_h;
        #pragma unroll
        for (int j = 0; j < 4; j++) {
            int i = blk2 * 256 + tid + j * 8192;
            float4 x = in[i];
            union { uint2 u; __half2 h[2]; } cv;
            cv.h[0] = __floats2half2_rn(x.x, x.y);
            cv.h[1] = __floats2half2_rn(x.z, x.w);
            out[i] = cv.u;
        }
    } else if (blk == 288) {
        __shared__ int f;
        if (tid == 0) f = 0;
        __syncthreads();
        const uint4* m4 = (const uint4*)mask;
        uint32_t acc = 0;
        #pragma unroll 8
        for (int j = 0; j < 32; j++) {
            uint4 w = m4[tid + j * 256];
            acc |= (w.x | w.y | w.z | w.w) & 0xFFFFFF00u;
        }
        if (acc) atomicOr(&f, 1);
        __syncthreads();
        if (tid == 0) g_mask_is_byte = f;
    } else {
        float4 z = {0.f, 0.f, 0.f, 0.f};
        float4* o4 = (float4*)out_ctx;
        #pragma unroll
        for (int j = 0; j < 32; j++)
            o4[tid + j * 256] = z;
    }
}

// ---------------------------------------------------------------------------
// Persistent energy kernel (frozen best): fp16 WMMA 128x256x512, f32 accum,
// 64x64 warp tiles, warm pipeline across tiles, two-pass f32 epilogue.
// ---------------------------------------------------------------------------
__device__ __forceinline__ void tile_of(int gc, int bx, int& bb, int& tx) {
    const int tile_id = bx + (gc >> 3) * EGRID;
    tx = tile_id & (TPB - 1);
    bb = tile_id >> 4;
}

__device__ __forceinline__ void ldg_a(const float* __restrict__ enc, int gc,
                                      int bx, float4* r, int tid) {
    int bb, tx; tile_of(gc, bx, bb, tx);
    const float* p = enc + ((size_t)bb * T + tx * TILE_M) * ENC + (gc & 7) * KC;
    #pragma unroll
    for (int it = 0; it < 8; it++) {
        int idx = it * 256 + tid;
        int row = idx >> 4, col4 = idx & 15;
        r[it] = *(const float4*)(p + (size_t)row * ENC + col4 * 4);
    }
}

__device__ __forceinline__ void cvt_sts_a(const float4* r, int gc, int bx,
                                          __half* aslot, int tid) {
    int bb, tx; tile_of(gc, bx, bb, tx);
    __half* gdst = g_enc_h + ((size_t)bb * T + tx * TILE_M) * ENC + (gc & 7) * KC;
    #pragma unroll
    for (int it = 0; it < 8; it++) {
        int idx = it * 256 + tid;
        int row = idx >> 4, col4 = idx & 15;
        union { uint2 u; __half2 h[2]; } cv;
        cv.h[0] = __floats2half2_rn(r[it].x, r[it].y);
        cv.h[1] = __floats2half2_rn(r[it].z, r[it].w);
        *(uint2*)(aslot + row * A_LD_H + col4 * 4) = cv.u;
        *(uint2*)(gdst + (size_t)row * ENC + col4 * 4) = cv.u;
    }
}

__device__ __forceinline__ void load_b(int gc, uint32_t bslot_u, int tid) {
    const __half* bsrc = g_We_h + (size_t)(gc & 7) * KC * ATTN;
    #pragma unroll
    for (int it = 0; it < 8; it++) {
        int idx = it * 256 + tid;
        int row = idx >> 5, seg = idx & 31;
        cp_async16(bslot_u + (uint32_t)(row * B_LD_H + seg * 8) * 2,
                   bsrc + (size_t)row * ATTN + seg * 8);
    }
}

__global__ void __launch_bounds__(256, 1)
energy_wmma_kernel(const float* __restrict__ enc, const float* __restrict__ v) {
    extern __shared__ char dsm[];
    float* pd_s = (float*)dsm;
    float* v_s  = (float*)(dsm + ATTN * 4);
    float* c2_s = (float*)(dsm + C_OFF);

    const uint32_t sb = smem_u32(dsm);
    const int tid = threadIdx.x;
    const int wid = tid >> 5;
    const int wm  = wid & 1;
    const int wn  = wid >> 1;
    const int bx  = blockIdx.x;

    const int NT   = (NTILES - 1 - bx) / EGRID + 1;
    const int GTOT = NT * CPT;

    v_s[tid] = v[tid];

    wmma::fragment<wmma::accumulator, 16, 16, 16, float> cf[4][4];
    #pragma unroll
    for (int i = 0; i < 4; i++)
        #pragma unroll
        for (int j = 0; j < 4; j++)
            wmma::fill_fragment(cf[i][j], 0.0f);

    float4 rnext[8];

    ldg_a(enc, 0, bx, rnext, tid);
    load_b(0, sb + B0_OFF, tid);  CP_COMMIT();
    cvt_sts_a(rnext, 0, bx, (__half*)(dsm + A0_OFF), tid);
    ldg_a(enc, 1, bx, rnext, tid);
    load_b(1, sb + B0_OFF + B_SLOT_B, tid);  CP_COMMIT();
    CP_WAIT(1);
    __syncthreads();

    #pragma unroll 1
    for (int gc = 0; gc < GTOT; gc++) {
        if (gc + 1 < GTOT)
            cvt_sts_a(rnext, gc + 1, bx,
                      (__half*)(dsm + A0_OFF + ((gc + 1) & 1) * A_SLOT_B), tid);
        if (gc + 2 < GTOT)
            ldg_a(enc, gc + 2, bx, rnext, tid);

        const __half* a_s = (const __half*)(dsm + A0_OFF + (gc & 1) * A_SLOT_B);
        const __half* b_s = (const __half*)(dsm + B0_OFF + (gc & 1) * B_SLOT_B);
        #pragma unroll
        for (int ks = 0; ks < KC / 16; ks++) {
            wmma::fragment<wmma::matrix_a, 16, 16, 16, __half, wmma::row_major> af[4];
            #pragma unroll
            for (int i = 0; i < 4; i++)
                wmma::load_matrix_sync(af[i],
                    a_s + (size_t)(wm * 64 + i * 16) * A_LD_H + ks * 16, A_LD_H);
            #pragma unroll
            for (int j = 0; j < 4; j++) {
                wmma::fragment<wmma::matrix_b, 16, 16, 16, __half, wmma::row_major> bfrag;
                wmma::load_matrix_sync(bfrag,
                    b_s + (size_t)(ks * 16) * B_LD_H + wn * 64 + j * 16, B_LD_H);
                #pragma unroll
                for (int i = 0; i < 4; i++)
                    wmma::mma_sync(cf[i][j], af[i], bfrag, cf[i][j]);
            }
        }

        if (gc + 1 < GTOT) CP_WAIT(0);
        __syncthreads();
        if (gc + 2 < GTOT) {
            load_b(gc + 2, sb + B0_OFF + (gc & 1) * B_SLOT_B, tid);
            CP_COMMIT();
        }

        if ((gc & 7) == 7) {
            int bb, tx; tile_of(gc, bx, bb, tx);
            pd_s[tid] = g_proj_dec[bb * ATTN + tid];

            const int row = tid >> 1, h = tid & 1;
            float e = 0.f;
            #pragma unroll
            for (int p = 0; p < 2; p++) {
                __syncthreads();
                if ((wn >> 1) == p) {
                    #pragma unroll
                    for (int i = 0; i < 4; i++)
                        #pragma unroll
                        for (int j = 0; j < 4; j++)
                            wmma::store_matrix_sync(
                                c2_s + (size_t)(wm * 64 + i * 16) * C_LD2
                                     + (wn & 1) * 64 + j * 16,
                                cf[i][j], C_LD2, wmma::mem_row_major);
                }
                __syncthreads();
                const float* crow = c2_s + (size_t)row * C_LD2 + h * 64;
                const float* pdq  = pd_s + p * 128 + h * 64;
                const float* vq   = v_s + p * 128 + h * 64;
                #pragma unroll 8
                for (int j = 0; j < 64; j++)
                    e = fmaf(fast_tanh(crow[j] + pdq[j]), vq[j], e);
            }
            e += __shfl_xor_sync(0xffffffffu, e, 1);
            if (h == 0)
                g_energy[bb * T + tx * TILE_M + row] = e;

            #pragma unroll
            for (int i = 0; i < 4; i++)
                #pragma unroll
                for (int j = 0; j < 4; j++)
                    wmma::fill_fragment(cf[i][j], 0.0f);
            __syncthreads();
        }
    }
}

// ---------------------------------------------------------------------------
// Fused softmax + context partials: grid (B, CSEG), block 128.
// Phase 1 uses uint4 (16B) loads, 2 t-rows per iteration for higher MLP.
// Context accumulated straight into out_ctx via atomicAdd.
// ---------------------------------------------------------------------------
__global__ void __launch_bounds__(128)
ctx_softmax_kernel(const void* __restrict__ mask,
                   float* __restrict__ attn_out,
                   float* __restrict__ out_ctx) {
    __shared__ float sred[8];
    __shared__ float sw[CT];

    const int b   = blockIdx.x;
    const int seg = blockIdx.y;
    const int tb  = seg * CT;
    const int tid = threadIdx.x;

    const bool isbyte = (g_mask_is_byte != 0);
    const unsigned char* mb = (const unsigned char*)mask;
    const int*           mi = (const int*)mask;

    // ---- phase 0: full-row masked max + sum ----
    float e[16];
    #pragma unroll
    for (int j = 0; j < 16; j++) {
        const int i = b * T + tid + j * 128;
        const bool m = isbyte ? (mb[i] != 0) : (mi[i] != 0);
        e[j] = m ? -INFINITY : g_energy[i];
    }
    float mx = e[0];
    #pragma unroll
    for (int j = 1; j < 16; j++) mx = fmaxf(mx, e[j]);
    #pragma unroll
    for (int o = 16; o > 0; o >>= 1)
        mx = fmaxf(mx, __shfl_xor_sync(0xffffffffu, mx, o));
    if ((tid & 31) == 0) sred[tid >> 5] = mx;
    __syncthreads();
    if (tid < 32) {
        float t = (tid < 4) ? sred[tid] : -INFINITY;
        #pragma unroll
        for (int o = 2; o > 0; o >>= 1)
            t = fmaxf(t, __shfl_xor_sync(0xffffffffu, t, o));
        if (tid == 0) sred[4] = t;
    }
    __syncthreads();
    mx = sred[4];

    const bool allmasked = !(mx > -INFINITY);

    float s = 0.f;
    #pragma unroll
    for (int j = 0; j < 16; j++)
        s += (allmasked || e[j] == -INFINITY) ? 0.f : expf(e[j] - mx);
    #pragma unroll
    for (int o = 16; o > 0; o >>= 1)
        s += __shfl_xor_sync(0xffffffffu, s, o);
    __syncthreads();
    if ((tid & 31) == 0) sred[tid >> 5] = s;
    __syncthreads();
    if (tid < 32) {
        float t = (tid < 4) ? sred[tid] : 0.f;
        #pragma unroll
        for (int o = 2; o > 0; o >>= 1)
            t += __shfl_xor_sync(0xffffffffu, t, o);
        if (tid == 0) sred[5] = t;
    }
    __syncthreads();
    s = sred[5];
    const float inv = (s > 0.f) ? (1.f / s) : 0.f;

    if (tid < CT) {
        const int i = b * T + tb + tid;
        const bool m = isbyte ? (mb[i] != 0) : (mi[i] != 0);
        const float ev = (allmasked || m) ? -INFINITY : g_energy[i];
        const float w = (ev == -INFINITY) ? 0.f : expf(ev - mx) * inv;
        sw[tid] = w;
        attn_out[i] = w;
    }
    __syncthreads();

    // ---- phase 1: thread owns uint4 column (8 halves), 2 t-rows / iter ----
    const int col = tid & 63;          // uint4 column 0..63 (covers ENC=512)
    const int rp  = tid >> 6;          // row parity 0/1
    const uint4* ep = (const uint4*)(g_enc_h + ((size_t)b * T + tb) * ENC) + col;
    float4 acc0 = {0.f, 0.f, 0.f, 0.f};
    float4 acc1 = {0.f, 0.f, 0.f, 0.f};
    #pragma unroll 8
    for (int t = rp; t < CT; t += 2) {
        union { uint4 u; __half2 h[4]; } w;
        w.u = ep[(size_t)t * (ENC / 8)];
        const float sc = sw[t];
        float2 f0 = __half22float2(w.h[0]);
        float2 f1 = __half22float2(w.h[1]);
        float2 f2 = __half22float2(w.h[2]);
        float2 f3 = __half22float2(w.h[3]);
        acc0.x = fmaf(sc, f0.x, acc0.x);
        acc0.y = fmaf(sc, f0.y, acc0.y);
        acc0.z = fmaf(sc, f1.x, acc0.z);
        acc0.w = fmaf(sc, f1.y, acc0.w);
        acc1.x = fmaf(sc, f2.x, acc1.x);
        acc1.y = fmaf(sc, f2.y, acc1.y);
        acc1.z = fmaf(sc, f3.x, acc1.z);
        acc1.w = fmaf(sc, f3.y, acc1.w);
    }
    float* dst = out_ctx + b * ENC + col * 8;
    atomicAdd(dst + 0, acc0.x);
    atomicAdd(dst + 1, acc0.y);
    atomicAdd(dst + 2, acc0.z);
    atomicAdd(dst + 3, acc0.w);
    atomicAdd(dst + 4, acc1.x);
    atomicAdd(dst + 5, acc1.y);
    atomicAdd(dst + 6, acc1.z);
    atomicAdd(dst + 7, acc1.w);
}

// ---------------------------------------------------------------------------
extern "C" void kernel_launch(void* const* d_in, const int* in_sizes, int n_in,
                              void* d_out, int out_size) {
    const float* enc  = (const float*)d_in[0];
    const float* dec  = (const float*)d_in[1];
    const void*  mask = d_in[2];
    const float* We   = (const float*)d_in[3];
    const float* Wd   = (const float*)d_in[4];
    const float* v    = (const float*)d_in[5];

    float* out_ctx  = (float*)d_out;
    float* out_attn = out_ctx + B * ENC;

    cudaFuncSetAttribute(energy_wmma_kernel,
                         cudaFuncAttributeMaxDynamicSharedMemorySize, DYN_SMEM);

    prep_kernel<<<290, 256>>>(dec, Wd, We, (const unsigned char*)mask, out_ctx);
    energy_wmma_kernel<<<EGRID, 256, DYN_SMEM>>>(enc, v);
    ctx_softmax_kernel<<<dim3(B, CSEG), 128>>>(mask, out_attn, out_ctx);
}

// round 16
// speedup vs baseline: 1.1171x; 1.1171x over previous
#include <cuda_runtime.h>
#include <cuda_fp16.h>
#include <math.h>
#include <stdint.h>
#include <mma.h>

using namespace nvcuda;

// Problem constants
#define B    64
#define T    2048
#define ENC  512
#define DEC  512
#define ATTN 256

// Energy GEMM tiling: 128x256 CTA tile, 8 warps, warp tile 64x64, persistent
#define TILE_M  128
#define KC      64
#define CPT     8
#define NTILES  1024
#define TPB     16
#define EGRID   148

#define A_LD_H  72
#define B_LD_H  264
#define C_LD2   136

#define A_SLOT_B (TILE_M * A_LD_H * 2)
#define B_SLOT_B (KC * B_LD_H * 2)
#define META_B   2048
#define A0_OFF   META_B
#define B0_OFF   (META_B + 2 * A_SLOT_B)
#define C_OFF    (B0_OFF + 2 * B_SLOT_B)
#define C_BYTES  (TILE_M * C_LD2 * 4)
#define DYN_SMEM (C_OFF + C_BYTES)          // 176128

// Context split-T
#define CSEG     32
#define CT       (T / CSEG)        // 64

// ---- scratch (no allocations allowed) ----
__device__ __half g_enc_h[(size_t)B * T * ENC];
__device__ __half g_We_h[ENC * ATTN];
__device__ float  g_proj_dec[B * ATTN];
__device__ float  g_energy[B * T];
__device__ float  g_smax[B * 2];            // per-row {mx, inv}
__device__ int    g_mask_is_byte;

// ---------------------------------------------------------------------------
__device__ __forceinline__ uint32_t smem_u32(const void* p) {
    uint32_t a;
    asm("{ .reg .u64 t; cvta.to.shared.u64 t, %1; cvt.u32.u64 %0, t; }" : "=r"(a) : "l"(p));
    return a;
}
__device__ __forceinline__ float fast_tanh(float x) {
    float y; asm("tanh.approx.f32 %0, %1;" : "=f"(y) : "f"(x)); return y;
}
__device__ __forceinline__ void cp_async16(uint32_t s, const void* g) {
    asm volatile("cp.async.cg.shared.global [%0], [%1], 16;" :: "r"(s), "l"(g));
}
#define CP_COMMIT() asm volatile("cp.async.commit_group;" ::: "memory")
#define CP_WAIT(n)  asm volatile("cp.async.wait_group %0;" :: "n"(n) : "memory")

// ---------------------------------------------------------------------------
// Fused prologue (R14 exact): projdec (0-255), convert_we (256-287),
// mask detect (288), zero out_ctx (289).
// ---------------------------------------------------------------------------
__global__ void __launch_bounds__(256)
prep_kernel(const float* __restrict__ dec, const float* __restrict__ Wd,
            const float* __restrict__ We, const unsigned char* __restrict__ mask,
            float* __restrict__ out_ctx) {
    const int blk = blockIdx.x, tid = threadIdx.x;

    if (blk < 256) {
        __shared__ float sd[DEC];
        __shared__ float sp[256];
        const int b = blk >> 2, q = blk & 3;
        const int a = q * 64 + (tid & 63);
        const int kseg = tid >> 6;
        sd[tid]       = dec[b * DEC + tid];
        sd[tid + 256] = dec[b * DEC + tid + 256];
        __syncthreads();
        const float* wp = Wd + (size_t)(kseg * 128) * ATTN + a;
        const float* dp = sd + kseg * 128;
        float a0 = 0.f, a1 = 0.f, a2 = 0.f, a3 = 0.f;
        #pragma unroll 8
        for (int i = 0; i < 128; i += 4) {
            a0 = fmaf(dp[i + 0], wp[(size_t)(i + 0) * ATTN], a0);
            a1 = fmaf(dp[i + 1], wp[(size_t)(i + 1) * ATTN], a1);
            a2 = fmaf(dp[i + 2], wp[(size_t)(i + 2) * ATTN], a2);
            a3 = fmaf(dp[i + 3], wp[(size_t)(i + 3) * ATTN], a3);
        }
        sp[tid] = (a0 + a1) + (a2 + a3);
        __syncthreads();
        if (tid < 64)
            g_proj_dec[b * ATTN + q * 64 + tid] =
                sp[tid] + sp[tid + 64] + sp[tid + 128] + sp[tid + 192];
    } else if (blk < 288) {
        const int blk2 = blk - 256;
        const float4* in = (const float4*)We;
        uint2* out = (uint2*)g_We_h;
        #pragma unroll
        for (int j = 0; j < 4; j++) {
            int i = blk2 * 256 + tid + j * 8192;
            float4 x = in[i];
            union { uint2 u; __half2 h[2]; } cv;
            cv.h[0] = __floats2half2_rn(x.x, x.y);
            cv.h[1] = __floats2half2_rn(x.z, x.w);
            out[i] = cv.u;
        }
    } else if (blk == 288) {
        __shared__ int f;
        if (tid == 0) f = 0;
        __syncthreads();
        const uint4* m4 = (const uint4*)mask;
        uint32_t acc = 0;
        #pragma unroll 8
        for (int j = 0; j < 32; j++) {
            uint4 w = m4[tid + j * 256];
            acc |= (w.x | w.y | w.z | w.w) & 0xFFFFFF00u;
        }
        if (acc) atomicOr(&f, 1);
        __syncthreads();
        if (tid == 0) g_mask_is_byte = f;
    } else {
        float4 z = {0.f, 0.f, 0.f, 0.f};
        float4* o4 = (float4*)out_ctx;
        #pragma unroll
        for (int j = 0; j < 32; j++)
            o4[tid + j * 256] = z;
    }
}

// ---------------------------------------------------------------------------
// Persistent energy kernel (frozen best, R13/R14 exact).
// ---------------------------------------------------------------------------
__device__ __forceinline__ void tile_of(int gc, int bx, int& bb, int& tx) {
    const int tile_id = bx + (gc >> 3) * EGRID;
    tx = tile_id & (TPB - 1);
    bb = tile_id >> 4;
}

__device__ __forceinline__ void ldg_a(const float* __restrict__ enc, int gc,
                                      int bx, float4* r, int tid) {
    int bb, tx; tile_of(gc, bx, bb, tx);
    const float* p = enc + ((size_t)bb * T + tx * TILE_M) * ENC + (gc & 7) * KC;
    #pragma unroll
    for (int it = 0; it < 8; it++) {
        int idx = it * 256 + tid;
        int row = idx >> 4, col4 = idx & 15;
        r[it] = *(const float4*)(p + (size_t)row * ENC + col4 * 4);
    }
}

__device__ __forceinline__ void cvt_sts_a(const float4* r, int gc, int bx,
                                          __half* aslot, int tid) {
    int bb, tx; tile_of(gc, bx, bb, tx);
    __half* gdst = g_enc_h + ((size_t)bb * T + tx * TILE_M) * ENC + (gc & 7) * KC;
    #pragma unroll
    for (int it = 0; it < 8; it++) {
        int idx = it * 256 + tid;
        int row = idx >> 4, col4 = idx & 15;
        union { uint2 u; __half2 h[2]; } cv;
        cv.h[0] = __floats2half2_rn(r[it].x, r[it].y);
        cv.h[1] = __floats2half2_rn(r[it].z, r[it].w);
        *(uint2*)(aslot + row * A_LD_H + col4 * 4) = cv.u;
        *(uint2*)(gdst + (size_t)row * ENC + col4 * 4) = cv.u;
    }
}

__device__ __forceinline__ void load_b(int gc, uint32_t bslot_u, int tid) {
    const __half* bsrc = g_We_h + (size_t)(gc & 7) * KC * ATTN;
    #pragma unroll
    for (int it = 0; it < 8; it++) {
        int idx = it * 256 + tid;
        int row = idx >> 5, seg = idx & 31;
        cp_async16(bslot_u + (uint32_t)(row * B_LD_H + seg * 8) * 2,
                   bsrc + (size_t)row * ATTN + seg * 8);
    }
}

__global__ void __launch_bounds__(256, 1)
energy_wmma_kernel(const float* __restrict__ enc, const float* __restrict__ v) {
    extern __shared__ char dsm[];
    float* pd_s = (float*)dsm;
    float* v_s  = (float*)(dsm + ATTN * 4);
    float* c2_s = (float*)(dsm + C_OFF);

    const uint32_t sb = smem_u32(dsm);
    const int tid = threadIdx.x;
    const int wid = tid >> 5;
    const int wm  = wid & 1;
    const int wn  = wid >> 1;
    const int bx  = blockIdx.x;

    const int NT   = (NTILES - 1 - bx) / EGRID + 1;
    const int GTOT = NT * CPT;

    v_s[tid] = v[tid];

    wmma::fragment<wmma::accumulator, 16, 16, 16, float> cf[4][4];
    #pragma unroll
    for (int i = 0; i < 4; i++)
        #pragma unroll
        for (int j = 0; j < 4; j++)
            wmma::fill_fragment(cf[i][j], 0.0f);

    float4 rnext[8];

    ldg_a(enc, 0, bx, rnext, tid);
    load_b(0, sb + B0_OFF, tid);  CP_COMMIT();
    cvt_sts_a(rnext, 0, bx, (__half*)(dsm + A0_OFF), tid);
    ldg_a(enc, 1, bx, rnext, tid);
    load_b(1, sb + B0_OFF + B_SLOT_B, tid);  CP_COMMIT();
    CP_WAIT(1);
    __syncthreads();

    #pragma unroll 1
    for (int gc = 0; gc < GTOT; gc++) {
        if (gc + 1 < GTOT)
            cvt_sts_a(rnext, gc + 1, bx,
                      (__half*)(dsm + A0_OFF + ((gc + 1) & 1) * A_SLOT_B), tid);
        if (gc + 2 < GTOT)
            ldg_a(enc, gc + 2, bx, rnext, tid);

        const __half* a_s = (const __half*)(dsm + A0_OFF + (gc & 1) * A_SLOT_B);
        const __half* b_s = (const __half*)(dsm + B0_OFF + (gc & 1) * B_SLOT_B);
        #pragma unroll
        for (int ks = 0; ks < KC / 16; ks++) {
            wmma::fragment<wmma::matrix_a, 16, 16, 16, __half, wmma::row_major> af[4];
            #pragma unroll
            for (int i = 0; i < 4; i++)
                wmma::load_matrix_sync(af[i],
                    a_s + (size_t)(wm * 64 + i * 16) * A_LD_H + ks * 16, A_LD_H);
            #pragma unroll
            for (int j = 0; j < 4; j++) {
                wmma::fragment<wmma::matrix_b, 16, 16, 16, __half, wmma::row_major> bfrag;
                wmma::load_matrix_sync(bfrag,
                    b_s + (size_t)(ks * 16) * B_LD_H + wn * 64 + j * 16, B_LD_H);
                #pragma unroll
                for (int i = 0; i < 4; i++)
                    wmma::mma_sync(cf[i][j], af[i], bfrag, cf[i][j]);
            }
        }

        if (gc + 1 < GTOT) CP_WAIT(0);
        __syncthreads();
        if (gc + 2 < GTOT) {
            load_b(gc + 2, sb + B0_OFF + (gc & 1) * B_SLOT_B, tid);
            CP_COMMIT();
        }

        if ((gc & 7) == 7) {
            int bb, tx; tile_of(gc, bx, bb, tx);
            pd_s[tid] = g_proj_dec[bb * ATTN + tid];

            const int row = tid >> 1, h = tid & 1;
            float e = 0.f;
            #pragma unroll
            for (int p = 0; p < 2; p++) {
                __syncthreads();
                if ((wn >> 1) == p) {
                    #pragma unroll
                    for (int i = 0; i < 4; i++)
                        #pragma unroll
                        for (int j = 0; j < 4; j++)
                            wmma::store_matrix_sync(
                                c2_s + (size_t)(wm * 64 + i * 16) * C_LD2
                                     + (wn & 1) * 64 + j * 16,
                                cf[i][j], C_LD2, wmma::mem_row_major);
                }
                __syncthreads();
                const float* crow = c2_s + (size_t)row * C_LD2 + h * 64;
                const float* pdq  = pd_s + p * 128 + h * 64;
                const float* vq   = v_s + p * 128 + h * 64;
                #pragma unroll 8
                for (int j = 0; j < 64; j++)
                    e = fmaf(fast_tanh(crow[j] + pdq[j]), vq[j], e);
            }
            e += __shfl_xor_sync(0xffffffffu, e, 1);
            if (h == 0)
                g_energy[bb * T + tx * TILE_M + row] = e;

            #pragma unroll
            for (int i = 0; i < 4; i++)
                #pragma unroll
                for (int j = 0; j < 4; j++)
                    wmma::fill_fragment(cf[i][j], 0.0f);
            __syncthreads();
        }
    }
}

// ---------------------------------------------------------------------------
// Softmax stats: one block per batch row; writes {mx, inv} to g_smax.
// ---------------------------------------------------------------------------
__global__ void __launch_bounds__(256)
smax_stats_kernel(const void* __restrict__ mask) {
    __shared__ float sred[8];
    const int b = blockIdx.x, tid = threadIdx.x;
    const bool isbyte = (g_mask_is_byte != 0);
    const unsigned char* mb = (const unsigned char*)mask;
    const int*           mi = (const int*)mask;

    float e[8];
    #pragma unroll
    for (int j = 0; j < 8; j++) {
        const int i = b * T + tid + j * 256;
        const bool m = isbyte ? (mb[i] != 0) : (mi[i] != 0);
        e[j] = m ? -INFINITY : g_energy[i];
    }
    float mx = e[0];
    #pragma unroll
    for (int j = 1; j < 8; j++) mx = fmaxf(mx, e[j]);
    #pragma unroll
    for (int o = 16; o > 0; o >>= 1)
        mx = fmaxf(mx, __shfl_xor_sync(0xffffffffu, mx, o));
    if ((tid & 31) == 0) sred[tid >> 5] = mx;
    __syncthreads();
    if (tid < 32) {
        float t = (tid < 8) ? sred[tid] : -INFINITY;
        #pragma unroll
        for (int o = 4; o > 0; o >>= 1)
            t = fmaxf(t, __shfl_xor_sync(0xffffffffu, t, o));
        if (tid == 0) sred[0] = t;
    }
    __syncthreads();
    mx = sred[0];
    __syncthreads();

    const bool allmasked = !(mx > -INFINITY);

    float s = 0.f;
    #pragma unroll
    for (int j = 0; j < 8; j++)
        s += (allmasked || e[j] == -INFINITY) ? 0.f : expf(e[j] - mx);
    #pragma unroll
    for (int o = 16; o > 0; o >>= 1)
        s += __shfl_xor_sync(0xffffffffu, s, o);
    if ((tid & 31) == 0) sred[tid >> 5] = s;
    __syncthreads();
    if (tid < 32) {
        float t = (tid < 8) ? sred[tid] : 0.f;
        #pragma unroll
        for (int o = 4; o > 0; o >>= 1)
            t += __shfl_xor_sync(0xffffffffu, t, o);
        if (tid == 0) {
            g_smax[b * 2 + 0] = mx;
            g_smax[b * 2 + 1] = (t > 0.f) ? (1.f / t) : 0.f;
        }
    }
}

// ---------------------------------------------------------------------------
// Context + attn writeback: grid (B, CSEG), block 128.
// Reads precomputed {mx, inv}; phase-1 identical to R14 best (uint2 stream).
// ---------------------------------------------------------------------------
__global__ void __launch_bounds__(128)
ctx_kernel(const void* __restrict__ mask,
           float* __restrict__ attn_out,
           float* __restrict__ out_ctx) {
    __shared__ float sw[CT];

    const int b   = blockIdx.x;
    const int seg = blockIdx.y;
    const int tb  = seg * CT;
    const int tid = threadIdx.x;

    const bool isbyte = (g_mask_is_byte != 0);
    const unsigned char* mb = (const unsigned char*)mask;
    const int*           mi = (const int*)mask;

    const float mx  = g_smax[b * 2 + 0];
    const float inv = g_smax[b * 2 + 1];
    const bool allmasked = !(mx > -INFINITY);

    if (tid < CT) {
        const int i = b * T + tb + tid;
        const bool m = isbyte ? (mb[i] != 0) : (mi[i] != 0);
        float w = 0.f;
        if (!allmasked && !m)
            w = expf(g_energy[i] - mx) * inv;
        sw[tid] = w;
        attn_out[i] = w;
    }
    __syncthreads();

    const uint2* ep = (const uint2*)(g_enc_h + ((size_t)b * T + tb) * ENC) + tid;
    float4 acc = {0.f, 0.f, 0.f, 0.f};
    #pragma unroll 8
    for (int t = 0; t < CT; t++) {
        union { uint2 u; __half2 h[2]; } w;
        w.u = ep[(size_t)t * (ENC / 4)];
        const float sc = sw[t];
        float2 f0 = __half22float2(w.h[0]);
        float2 f1 = __half22float2(w.h[1]);
        acc.x = fmaf(sc, f0.x, acc.x);
        acc.y = fmaf(sc, f0.y, acc.y);
        acc.z = fmaf(sc, f1.x, acc.z);
        acc.w = fmaf(sc, f1.y, acc.w);
    }
    float* dst = out_ctx + b * ENC + tid * 4;
    atomicAdd(dst + 0, acc.x);
    atomicAdd(dst + 1, acc.y);
    atomicAdd(dst + 2, acc.z);
    atomicAdd(dst + 3, acc.w);
}

// ---------------------------------------------------------------------------
extern "C" void kernel_launch(void* const* d_in, const int* in_sizes, int n_in,
                              void* d_out, int out_size) {
    const float* enc  = (const float*)d_in[0];
    const float* dec  = (const float*)d_in[1];
    const void*  mask = d_in[2];
    const float* We   = (const float*)d_in[3];
    const float* Wd   = (const float*)d_in[4];
    const float* v    = (const float*)d_in[5];

    float* out_ctx  = (float*)d_out;
    float* out_attn = out_ctx + B * ENC;

    cudaFuncSetAttribute(energy_wmma_kernel,
                         cudaFuncAttributeMaxDynamicSharedMemorySize, DYN_SMEM);

    prep_kernel<<<290, 256>>>(dec, Wd, We, (const unsigned char*)mask, out_ctx);
    energy_wmma_kernel<<<EGRID, 256, DYN_SMEM>>>(enc, v);
    smax_stats_kernel<<<B, 256>>>(mask);
    ctx_kernel<<<dim3(B, CSEG), 128>>>(mask, out_attn, out_ctx);
}